// round 4
// baseline (speedup 1.0000x reference)
#include <cuda_runtime.h>
#include <math.h>

#define NNODES 50000
#define KNB 32
#define NLAT 10
#define NB 4
#define PADW 12           // dec_w rows padded 10 -> 12 floats (48B, 16B-aligned)
#define NCHUNK 64
#define UPB 8
#define CHSZ 784          // 784*64 = 50176 >= 50000

__device__ float g_decw[NNODES * PADW];     // padded dec_w
__device__ float g_part[NCHUNK * 800];      // GEMV partials [chunk][b*200+u]
__device__ float g_Htab[NB * 256];          // sigmoid table per (b, cluster)
__device__ float g_e[NB * NLAT];            // latent e

// ---------------------------------------------------------------- k_prep
__global__ void k_prep(const float* __restrict__ dec_w) {
    int idx = blockIdx.x * blockDim.x + threadIdx.x;
    if (idx < NNODES * PADW) {
        int n = idx / PADW, l = idx - n * PADW;
        g_decw[idx] = (l < NLAT) ? dec_w[n * NLAT + l] : 0.0f;
    }
}

// ---------------------------------------------------------------- k_gemv
// partial dots for z_raw[b][u] = sum_i x[b][i] * enc1_w[u][i]
__global__ __launch_bounds__(256) void k_gemv(const float* __restrict__ x,
                                              const float* __restrict__ w) {
    int u0 = blockIdx.x * UPB;
    int c  = blockIdx.y;
    int i0 = c * CHSZ;
    int iend = min(i0 + CHSZ, NNODES);

    float acc[UPB][NB];
#pragma unroll
    for (int u = 0; u < UPB; u++)
#pragma unroll
        for (int b = 0; b < NB; b++) acc[u][b] = 0.0f;

    for (int i = i0 + threadIdx.x; i < iend; i += 256) {
        float xv[NB];
#pragma unroll
        for (int b = 0; b < NB; b++) xv[b] = __ldg(&x[b * NNODES + i]);
#pragma unroll
        for (int u = 0; u < UPB; u++) {
            float wv = __ldg(&w[(u0 + u) * NNODES + i]);
#pragma unroll
            for (int b = 0; b < NB; b++) acc[u][b] = fmaf(wv, xv[b], acc[u][b]);
        }
    }

    __shared__ float sred[UPB * NB * 8];
    int wid = threadIdx.x >> 5, lane = threadIdx.x & 31;
#pragma unroll
    for (int u = 0; u < UPB; u++)
#pragma unroll
        for (int b = 0; b < NB; b++) {
            float v = acc[u][b];
            for (int o = 16; o; o >>= 1) v += __shfl_down_sync(0xffffffffu, v, o);
            if (lane == 0) sred[(u * NB + b) * 8 + wid] = v;
        }
    __syncthreads();
    if (threadIdx.x < UPB * NB) {
        int u = threadIdx.x / NB, b = threadIdx.x - u * NB;
        float s = 0.0f;
#pragma unroll
        for (int q = 0; q < 8; q++) s += sred[threadIdx.x * 8 + q];
        g_part[c * 800 + b * 200 + (u0 + u)] = s;
    }
}

// ---------------------------------------------------------------- k_mid
// finishes z (silu), then e, h1, h2, h3, sigmoid table. Single block.
__global__ void k_mid(const float* __restrict__ enc1_b,
                      const float* __restrict__ enc2_w, const float* __restrict__ enc2_b,
                      const float* __restrict__ h1_w, const float* __restrict__ h1_b,
                      const float* __restrict__ h2_w, const float* __restrict__ h2_b,
                      const float* __restrict__ h3_w, const float* __restrict__ h3_b) {
    __shared__ float sz[800];
    __shared__ float se[40];
    __shared__ float sh1[256];
    __shared__ float sh2[256];
    int tid = threadIdx.x;

    for (int idx = tid; idx < 800; idx += 256) {
        float s = 0.0f;
        for (int c = 0; c < NCHUNK; c++) s += g_part[c * 800 + idx];
        int u = idx % 200;
        s += enc1_b[u];
        sz[idx] = s / (1.0f + expf(-s));   // silu
    }
    __syncthreads();

    if (tid < 40) {
        int b = tid / 10, v = tid - b * 10;
        float s = enc2_b[v];
        for (int u = 0; u < 200; u++) s = fmaf(sz[b * 200 + u], enc2_w[v * 200 + u], s);
        se[tid] = s;
        g_e[tid] = s;
    }
    __syncthreads();

    {
        int b = tid >> 6, m = tid & 63;
        float s = h1_b[m];
#pragma unroll
        for (int v = 0; v < 10; v++) s = fmaf(se[b * 10 + v], h1_w[m * 10 + v], s);
        sh1[tid] = s / (1.0f + expf(-s));
    }
    __syncthreads();
    {
        int b = tid >> 6, m = tid & 63;
        float s = h2_b[m];
#pragma unroll
        for (int j = 0; j < 64; j++) s = fmaf(sh1[b * 64 + j], h2_w[m * 64 + j], s);
        sh2[tid] = s / (1.0f + expf(-s));
    }
    __syncthreads();
    for (int i = 0; i < 4; i++) {
        int idx = i * 256 + tid;
        int b = idx >> 8, cc = idx & 255;
        float s = h3_b[cc];
#pragma unroll
        for (int j = 0; j < 64; j++) s = fmaf(sh2[b * 64 + j], h3_w[cc * 64 + j], s);
        g_Htab[idx] = 1.0f / (1.0f + expf(-0.005f * s));
    }
}

// ---------------------------------------------------------------- k_main
// per-node: gather 32 neighbour dec_w rows, build A_l, B_l, S0; closed-form
// unclamped normalization; guarded exact fallback when clamping could bite.
__global__ __launch_bounds__(128) void k_main(const int* __restrict__ nb_id,
                                              const float* __restrict__ nb_dist,
                                              const int* __restrict__ labels,
                                              const float* __restrict__ dec_b,
                                              const float* __restrict__ Bparam,
                                              float* __restrict__ out) {
    __shared__ float sH[NB * 256];
    __shared__ float se[NB * NLAT];
    int tid = threadIdx.x;
    for (int i = tid; i < NB * 256; i += 128) sH[i] = g_Htab[i];
    if (tid < NB * NLAT) se[tid] = g_e[tid];
    __syncthreads();

    int node = blockIdx.x * 128 + tid;
    if (node >= NNODES) return;

    float Bp = __ldg(Bparam);
    float invB2 = __fdividef(1.0f, Bp * Bp);
    int label = __ldg(&labels[node]);

    float inv[NB][NLAT];
#pragma unroll
    for (int b = 0; b < NB; b++) {
        float H = sH[b * 256 + label];
        float base = 1.0f - 0.5f * H;
        float ib = __fdividef(1.0f, base * base);
        float v = invB2 * ib;           // l = 0  -> 1/(B^2 base^2)
        inv[b][0] = v;
#pragma unroll
        for (int l = 1; l < NLAT; l++) { v *= ib; inv[b][l] = v; }
    }

    float A[NLAT], Bv[NLAT];
#pragma unroll
    for (int l = 0; l < NLAT; l++) { A[l] = 0.0f; Bv[l] = 0.0f; }
    float S0 = 0.0f, d2max = 0.0f;

    const int4*   idp = (const int4*)(nb_id + node * KNB);
    const float4* dp  = (const float4*)(nb_dist + node * KNB);
#pragma unroll 2
    for (int kq = 0; kq < KNB / 4; kq++) {
        int4   iv = __ldg(idp + kq);
        float4 dv = __ldg(dp + kq);
        int   ida[4] = {iv.x, iv.y, iv.z, iv.w};
        float da[4]  = {dv.x, dv.y, dv.z, dv.w};
#pragma unroll
        for (int j = 0; j < 4; j++) {
            float d2 = da[j] * da[j];
            S0 += d2;
            d2max = fmaxf(d2max, d2);
            const float4* rp = (const float4*)(g_decw + ida[j] * PADW);
            float4 r0 = __ldg(rp);
            float4 r1 = __ldg(rp + 1);
            float4 r2 = __ldg(rp + 2);
            float r[NLAT] = {r0.x, r0.y, r0.z, r0.w, r1.x, r1.y, r1.z, r1.w, r2.x, r2.y};
#pragma unroll
            for (int l = 0; l < NLAT; l++) {
                A[l] += r[l];
                Bv[l] = fmaf(d2, r[l], Bv[l]);
            }
        }
    }

    float db = __ldg(&dec_b[node]);
#pragma unroll
    for (int b = 0; b < NB; b++) {
        float o = 0.0f;
        if (inv[b][NLAT - 1] * d2max <= 1.0f) {
            // fast path: no clamping possible for any l (inv is monotone in l)
#pragma unroll
            for (int l = 0; l < NLAT; l++) {
                float iw = inv[b][l];
                float s = fmaf(-iw, S0, (float)KNB);
                float t = fmaf(-iw, Bv[l], A[l]);
                o = fmaf(se[b * NLAT + l], __fdividef(t, s), o);
            }
        } else {
            // exact fallback with clamping (practically never taken)
            float ss[NLAT], tt[NLAT];
#pragma unroll
            for (int l = 0; l < NLAT; l++) { ss[l] = 0.0f; tt[l] = 0.0f; }
            for (int k = 0; k < KNB; k++) {
                int id = __ldg(nb_id + node * KNB + k);
                float d = __ldg(nb_dist + node * KNB + k);
                float d2 = d * d;
#pragma unroll
                for (int l = 0; l < NLAT; l++) {
                    float win = fmaxf(0.0f, fmaf(-inv[b][l], d2, 1.0f));
                    ss[l] += win;
                    tt[l] = fmaf(g_decw[id * PADW + l], win, tt[l]);
                }
            }
#pragma unroll
            for (int l = 0; l < NLAT; l++)
                o = fmaf(se[b * NLAT + l], __fdividef(tt[l], ss[l]), o);
        }
        out[b * NNODES + node] = o + db;
    }
}

// ---------------------------------------------------------------- launch
extern "C" void kernel_launch(void* const* d_in, const int* in_sizes, int n_in,
                              void* d_out, int out_size) {
    const float* x       = (const float*)d_in[0];
    const int*   nb_id   = (const int*)  d_in[1];
    const float* nb_dist = (const float*)d_in[2];
    const int*   labels  = (const int*)  d_in[3];
    const float* enc1_w  = (const float*)d_in[4];
    const float* enc1_b  = (const float*)d_in[5];
    const float* enc2_w  = (const float*)d_in[6];
    const float* enc2_b  = (const float*)d_in[7];
    const float* dec_w   = (const float*)d_in[8];
    const float* dec_b   = (const float*)d_in[9];
    const float* h1_w    = (const float*)d_in[10];
    const float* h1_b    = (const float*)d_in[11];
    const float* h2_w    = (const float*)d_in[12];
    const float* h2_b    = (const float*)d_in[13];
    const float* h3_w    = (const float*)d_in[14];
    const float* h3_b    = (const float*)d_in[15];
    const float* Bp      = (const float*)d_in[16];
    float* out = (float*)d_out;

    k_prep<<<(NNODES * PADW + 255) / 256, 256>>>(dec_w);
    dim3 g(200 / UPB, NCHUNK);
    k_gemv<<<g, 256>>>(x, enc1_w);
    k_mid<<<1, 256>>>(enc1_b, enc2_w, enc2_b, h1_w, h1_b, h2_w, h2_b, h3_w, h3_b);
    k_main<<<(NNODES + 127) / 128, 128>>>(nb_id, nb_dist, labels, dec_b, Bp, out);
}